// round 13
// baseline (speedup 1.0000x reference)
#include <cuda_runtime.h>
#include <cuda_fp16.h>
#include <math.h>
#include <stdint.h>

#define B_   4096
#define J_   32
#define E_   256
#define ROWS (B_ * J_)
#define NC1   (B_ / 32)              // 128 c1 CTAs (M=32 each)
#define NPREP (NC1 + 1)              // + 1 c2 CTA
#define NMAIN (ROWS / 128)           // 1024 main CTAs

// ======================= scratch (device globals) ==========================
__device__ float  g_c1[B_ * E_];         // bias + x @ W^T
__device__ float  g_c2[J_ * E_];         // keys @ V^T
__device__ float  g_zero[E_];            // zero "bias" for the c2 CTA
__device__ __half g_Uh[E_ * E_];         // U converted to fp16 (by prep)
__device__ unsigned int g_prep_done;
__device__ unsigned int g_main_done;

// ======================= PTX helpers =======================================
__device__ __forceinline__ uint32_t smem_u32(const void* p) {
    uint32_t a;
    asm("{ .reg .u64 t; cvta.to.shared.u64 t, %1; cvt.u32.u64 %0, t; }"
        : "=r"(a) : "l"(p));
    return a;
}

#define CP_ASYNC16(dst, src)                                                  \
    asm volatile("cp.async.cg.shared.global [%0], [%1], 16;"                  \
        :: "r"(dst), "l"(__cvta_generic_to_global((const void*)(src))) : "memory")

#define MBAR_INIT(addr, cnt)                                                  \
    asm volatile("mbarrier.init.shared.b64 [%0], %1;" :: "r"(addr), "r"(cnt) : "memory")
#define CP_MBAR_ARRIVE(addr)                                                  \
    asm volatile("cp.async.mbarrier.arrive.noinc.shared.b64 [%0];"            \
        :: "r"(addr) : "memory")
#define MBAR_ARRIVE(addr)                                                     \
    asm volatile("mbarrier.arrive.shared.b64 _, [%0];" :: "r"(addr) : "memory")
#define MBAR_WAIT(addr, parity) do {                                          \
    asm volatile("{\n\t.reg .pred P;\n\t"                                     \
        "WL_%=:\n\t"                                                          \
        "mbarrier.try_wait.parity.shared.b64 P, [%0], %1;\n\t"                \
        "@P bra.uni WD_%=;\n\t"                                               \
        "bra.uni WL_%=;\n\t"                                                  \
        "WD_%=:\n\t}"                                                         \
        :: "r"(addr), "r"(parity) : "memory");                                \
} while (0)

__device__ __forceinline__ void mma_tf32(float* d, const uint32_t* a,
                                         const uint32_t* b) {
    asm volatile(
        "mma.sync.aligned.m16n8k8.row.col.f32.tf32.tf32.f32 "
        "{%0,%1,%2,%3}, {%4,%5,%6,%7}, {%8,%9}, {%0,%1,%2,%3};"
        : "+f"(d[0]), "+f"(d[1]), "+f"(d[2]), "+f"(d[3])
        : "r"(a[0]), "r"(a[1]), "r"(a[2]), "r"(a[3]), "r"(b[0]), "r"(b[1]));
}
__device__ __forceinline__ void mma_f16(float* d, const uint32_t* a,
                                        const uint32_t* b) {
    asm volatile(
        "mma.sync.aligned.m16n8k16.row.col.f32.f16.f16.f32 "
        "{%0,%1,%2,%3}, {%4,%5,%6,%7}, {%8,%9}, {%0,%1,%2,%3};"
        : "+f"(d[0]), "+f"(d[1]), "+f"(d[2]), "+f"(d[3])
        : "r"(a[0]), "r"(a[1]), "r"(a[2]), "r"(a[3]), "r"(b[0]), "r"(b[1]));
}

__device__ __forceinline__ void ldsm_x4(uint32_t* r, uint32_t addr) {
    asm volatile("ldmatrix.sync.aligned.m8n8.x4.shared.b16 {%0,%1,%2,%3}, [%4];"
        : "=r"(r[0]), "=r"(r[1]), "=r"(r[2]), "=r"(r[3]) : "r"(addr));
}
__device__ __forceinline__ void ldsm_x2(uint32_t* r, uint32_t addr) {
    asm volatile("ldmatrix.sync.aligned.m8n8.x2.shared.b16 {%0,%1}, [%2];"
        : "=r"(r[0]), "=r"(r[1]) : "r"(addr));
}

// ======================= smem layout =======================================
#define NCH   16                     // K chunks of 16
// ---- main CTA (fp16 path) ----
#define PAHB  528                    // A fp16 row pitch in BYTES (264 halves)
#define PBHB  48                     // B fp16 row pitch in BYTES (24 halves)
#define BSTGB 12288                  // bytes per B stage (256*48)
#define AH_B  0                      // A fp16 tile base (byte offset)
#define BF_F  16896                  // float ofs of B stages (A = 128*528B)
#define XF_F  29184                  // x tile (4x256 fp32)
#define GD_F  30208                  // gate dot partials (128*2)
#define GF_F  30464                  // gate[128]
#define RED_F 30592                  // norm red[128*4]
#define INV_F 31104                  // inv[128]
#define MBR_F 31232                  // 8 mbarriers
#define SMEMF (MBR_F + 16)
#define MAIN_SMEM (SMEMF * 4)        // 124,992 bytes
// ---- prep CTA (tf32 path, unchanged from R12) ----
#define PA    260
#define PB    20
#define BSTG  5120
#define AF1   8320
#define XF1   (AF1 + 4 * BSTG)       // 28800
#define MB1F  (XF1 + 256)            // 29056  (< SMEMF ✓)

__device__ __forceinline__ void init_ring(uint32_t mb, int tid, int cnt)
{
    if (tid == 0) {
        #pragma unroll
        for (int s = 0; s < 4; ++s) {
            MBAR_INIT(mb + s * 8u, cnt);
            MBAR_INIT(mb + 32u + s * 8u, cnt);
        }
    }
    __syncthreads();
}

// ======================= main-CTA body (fp16 mma) ==========================
// B producer: chunk p of g_Uh (k local to stage), 1 cp.async(16B)/thread.
__device__ __forceinline__ void produce_h(uint32_t sb, uint32_t mb,
                                          int tid, int p)
{
    uint32_t bst = sb + (uint32_t)BF_F * 4u + (uint32_t)(p & 3) * BSTGB;
    int f = tid >> 1, hf = tid & 1;
    CP_ASYNC16(bst + (uint32_t)(f * PBHB + hf * 16),
               (const __half*)g_Uh + (size_t)f * E_ + p * 16 + hf * 8);
    CP_MBAR_ARRIVE(mb + (uint32_t)(p & 3) * 8u);
}

__device__ void main_body(const float* __restrict__ state,
                          const float* __restrict__ x,
                          const float* __restrict__ keys,
                          float* __restrict__ out,
                          float* sm, int bid)
{
    const int tid  = threadIdx.x;
    const int lane = tid & 31;
    const int wid  = tid >> 5;
    const int grp  = lane >> 2;
    const int tig  = lane & 3;
    const int mwarp = wid >> 2;       // 0..3 (32 rows)
    const int nwarp = wid & 3;        // 0..3 (64 cols)
    const int row0 = bid * 128;
    const uint32_t sb = smem_u32(sm);
    const uint32_t mb  = sb + (uint32_t)MBR_F * 4u;
    const uint32_t mbe = mb + 32u;
    char* smc = reinterpret_cast<char*>(sm);

    init_ring(mb, tid, 512);

    // ---- stage x (4 rows x 256 fp32) ----
    if (tid < 256)
        reinterpret_cast<float4*>(sm + XF_F)[tid] =
            reinterpret_cast<const float4*>(x + (size_t)(row0 >> 5) * E_)[tid];
    __syncthreads();

    // ---- A conversion pass: LDG state fp32 -> gate dot (fp32) -> STS fp16 --
    // warp w, iter i: row r = (w>>1) + 8i (all lanes), half hf = w&1.
    {
        float* gd = sm + GD_F;
        #pragma unroll 1
        for (int i = 0; i < 16; ++i) {
            int idx = tid + (i << 9);
            int r = idx >> 6, c4 = idx & 63;
            float4 sv = reinterpret_cast<const float4*>(
                            state + (size_t)(row0 + r) * E_)[c4];
            float4 xv = reinterpret_cast<const float4*>(
                            sm + XF_F + (r >> 5) * 256)[c4];
            float p = sv.x * xv.x + sv.y * xv.y + sv.z * xv.z + sv.w * xv.w;
            #pragma unroll
            for (int o = 16; o; o >>= 1) p += __shfl_xor_sync(0xffffffffu, p, o);
            if (lane == 0) gd[r * 2 + (wid & 1)] = p;
            __half2 h0 = __floats2half2_rn(sv.x, sv.y);
            __half2 h1 = __floats2half2_rn(sv.z, sv.w);
            uint2 u; u.x = *(uint32_t*)&h0; u.y = *(uint32_t*)&h1;
            *reinterpret_cast<uint2*>(smc + AH_B + r * PAHB + c4 * 8) = u;
        }
    }
    __syncthreads();

    // ---- wait prep (needs g_Uh before the B ring) ----
    if (tid == 0)
        while (atomicAdd(&g_prep_done, 0u) < (unsigned)NPREP) {}
    __syncthreads();

    float acc[2][8][4];
    #pragma unroll
    for (int mt = 0; mt < 2; ++mt)
        #pragma unroll
        for (int nt = 0; nt < 8; ++nt)
            #pragma unroll
            for (int q = 0; q < 4; ++q) acc[mt][nt][q] = 0.f;

    // ldmatrix lane-address bases (bytes)
    const uint32_t a_base = sb + AH_B
        + (uint32_t)((mwarp * 32 + (lane & 15)) * PAHB + ((lane >> 4) << 4));
    const uint32_t b_lane =
        (uint32_t)((nwarp * 64 + (lane & 7)) * PBHB + (((lane >> 3) & 1) << 4));

    produce_h(sb, mb, tid, 0);
    produce_h(sb, mb, tid, 1);
    produce_h(sb, mb, tid, 2);

    #pragma unroll 1
    for (int c = 0; c < NCH; ++c) {
        int cp = c + 3;
        if (cp < NCH) {
            int q2 = cp >> 2;
            if (q2 >= 1)
                MBAR_WAIT(mbe + (uint32_t)(cp & 3) * 8u, (q2 - 1) & 1);
            produce_h(sb, mb, tid, cp);
        }
        MBAR_WAIT(mb + (uint32_t)(c & 3) * 8u, (c >> 2) & 1);

        const uint32_t a_c = a_base + (uint32_t)c * 32u;       // A: global k
        const uint32_t b_c = sb + (uint32_t)BF_F * 4u
                           + (uint32_t)(c & 3) * BSTGB + b_lane;
        uint32_t afr[2][4];
        ldsm_x4(afr[0], a_c);
        ldsm_x4(afr[1], a_c + 16u * PAHB);
        uint32_t bfr[8][2];
        #pragma unroll
        for (int nt = 0; nt < 8; ++nt)
            ldsm_x2(bfr[nt], b_c + (uint32_t)nt * (8u * PBHB));
        #pragma unroll
        for (int nt = 0; nt < 8; ++nt) {
            mma_f16(acc[0][nt], afr[0], bfr[nt]);
            mma_f16(acc[1][nt], afr[1], bfr[nt]);
        }
        MBAR_ARRIVE(mbe + (uint32_t)(c & 3) * 8u);
    }

    __syncthreads();   // all warps out of the mainloop (A + B stages quiesce)

    // ---- stage keys (32x256 fp32, pitch 260) into the dead B area ----
    #pragma unroll
    for (int i = 0; i < 4; ++i) {
        int idx = tid + (i << 9);
        int r = idx >> 6, c4 = idx & 63;
        *reinterpret_cast<float4*>(sm + BF_F + r * PA + c4 * 4) =
            reinterpret_cast<const float4*>(keys + (size_t)r * E_)[c4];
    }
    __syncthreads();

    // ---- gate: sigma( x.s (from conversion pass) + x.key ), 4 thr/row ----
    {
        int r = tid >> 2, q = tid & 3;
        const float* krow = sm + BF_F + (r & 31) * PA;
        const float* xrow = sm + XF_F + (r >> 5) * 256;
        float dot = 0.f;
        #pragma unroll
        for (int u = 0; u < 16; ++u) {
            int f4 = u * 4 + q;
            float4 kv = *reinterpret_cast<const float4*>(krow + f4 * 4);
            float4 xv = *reinterpret_cast<const float4*>(xrow + f4 * 4);
            dot += kv.x * xv.x + kv.y * xv.y + kv.z * xv.z + kv.w * xv.w;
        }
        dot += __shfl_xor_sync(0xffffffffu, dot, 1);
        dot += __shfl_xor_sync(0xffffffffu, dot, 2);
        if (q == 0) {
            float ds = sm[GD_F + r * 2] + sm[GD_F + r * 2 + 1];
            sm[GF_F + r] = 1.f / (1.f + expf(-(ds + dot)));
        }
    }
    __syncthreads();

    // ---- epilogue pass 1: v = s + g*relu(acc + c1 + c2) -> Ah (fp16) ----
    float* red = sm + RED_F;
    float* inv = sm + INV_F;
    #pragma unroll
    for (int mt = 0; mt < 2; ++mt) {
        #pragma unroll
        for (int r2 = 0; r2 < 2; ++r2) {
            int rl   = mwarp * 32 + mt * 16 + grp + r2 * 8;
            int grow = row0 + rl;
            float gv = sm[GF_F + rl];
            const float* c1r = g_c1 + (size_t)(grow >> 5) * E_;
            const float* c2r = g_c2 + (size_t)(grow & 31) * E_;
            float ss = 0.f;
            #pragma unroll
            for (int nt = 0; nt < 8; ++nt) {
                int col = nwarp * 64 + nt * 8 + tig * 2;
                uint32_t su = *reinterpret_cast<uint32_t*>(
                                  smc + AH_B + rl * PAHB + col * 2);
                float2 svv = __half22float2(*reinterpret_cast<__half2*>(&su));
                float2 c1v = *reinterpret_cast<const float2*>(c1r + col);
                float2 c2v = *reinterpret_cast<const float2*>(c2r + col);
                float d0 = acc[mt][nt][r2 * 2 + 0] + c1v.x + c2v.x;
                float d1 = acc[mt][nt][r2 * 2 + 1] + c1v.y + c2v.y;
                float v0 = svv.x + gv * fmaxf(d0, 0.f);
                float v1 = svv.y + gv * fmaxf(d1, 0.f);
                ss += v0 * v0 + v1 * v1;
                __half2 hv = __floats2half2_rn(v0, v1);
                *reinterpret_cast<uint32_t*>(smc + AH_B + rl * PAHB + col * 2)
                    = *(uint32_t*)&hv;
            }
            ss += __shfl_xor_sync(0xffffffffu, ss, 1);
            ss += __shfl_xor_sync(0xffffffffu, ss, 2);
            if (tig == 0) red[rl * 4 + nwarp] = ss;
        }
    }
    __syncthreads();
    if (tid < 128) {
        float s = red[tid * 4] + red[tid * 4 + 1]
                + red[tid * 4 + 2] + red[tid * 4 + 3];
        inv[tid] = 1.f / (sqrtf(s) + 1e-8f);
    }
    __syncthreads();

    // ---- epilogue pass 2: coalesced normalized writeback (fp16 -> fp32) ---
    #pragma unroll
    for (int i = 0; i < 8; ++i) {
        int idx = tid + (i << 9);
        int r = idx >> 5, c8 = idx & 31;
        float iv = inv[r];
        uint4 u = *reinterpret_cast<uint4*>(smc + AH_B + r * PAHB + c8 * 16);
        const __half2* hp = reinterpret_cast<const __half2*>(&u);
        float4 o0, o1;
        float2 f0 = __half22float2(hp[0]), f1 = __half22float2(hp[1]);
        float2 f2 = __half22float2(hp[2]), f3 = __half22float2(hp[3]);
        o0 = make_float4(f0.x * iv, f0.y * iv, f1.x * iv, f1.y * iv);
        o1 = make_float4(f2.x * iv, f2.y * iv, f3.x * iv, f3.y * iv);
        float4* op = reinterpret_cast<float4*>(out + (size_t)(row0 + r) * E_
                                               + c8 * 8);
        op[0] = o0; op[1] = o1;
    }

    // ---- last main CTA resets the handshake counters ----
    __syncthreads();
    if (tid == 0) {
        unsigned v = atomicAdd(&g_main_done, 1u);
        if (v == (unsigned)(NMAIN - 1)) {
            atomicExch(&g_prep_done, 0u);
            atomicExch(&g_main_done, 0u);
        }
    }
}

// ======================= prep-CTA body (tf32 M=32, unchanged) ==============
__device__ __forceinline__ void produce_prep(const float* __restrict__ Bg,
                                             uint32_t sb, uint32_t mb,
                                             int tid, int p)
{
    uint32_t bst = sb + (uint32_t)(AF1 + (p & 3) * BSTG) * 4u;
    #pragma unroll
    for (int i = 0; i < 2; ++i) {
        int idx = tid + (i << 9);
        int f = idx >> 2, k4 = idx & 3;
        CP_ASYNC16(bst + (uint32_t)(f * PB + k4 * 4) * 4u,
                   Bg + (size_t)f * E_ + p * 16 + k4 * 4);
    }
    CP_MBAR_ARRIVE(mb + (uint32_t)(p & 3) * 8u);
}

__device__ void prep_body(const float* __restrict__ A,
                          const float* __restrict__ Bmat,
                          const float* __restrict__ bias,
                          float* __restrict__ outp, int row0,
                          float* sm)
{
    const int tid  = threadIdx.x;
    const int lane = tid & 31;
    const int wid  = tid >> 5;
    const int grp  = lane >> 2;
    const int tig  = lane & 3;
    const int mwarp = wid >> 3;       // 0..1 (16 rows each)
    const int nwarp = wid & 7;        // 0..7 (32 cols each)
    const uint32_t sb = smem_u32(sm);
    const uint32_t mb  = sb + (uint32_t)MB1F * 4u;
    const uint32_t mbe = mb + 32u;

    init_ring(mb, tid, 512);

    #pragma unroll
    for (int i = 0; i < 4; ++i) {
        int idx = tid + (i << 9);
        int r = idx >> 6, c4 = idx & 63;
        CP_ASYNC16(sb + (uint32_t)(r * PA + c4 * 4) * 4u,
                   A + (size_t)(row0 + r) * E_ + c4 * 4);
    }
    if (tid < 64)
        CP_ASYNC16(sb + (uint32_t)(XF1 + tid * 4) * 4u, bias + tid * 4);

    float acc[4][4];
    #pragma unroll
    for (int nt = 0; nt < 4; ++nt)
        #pragma unroll
        for (int q = 0; q < 4; ++q) acc[nt][q] = 0.f;

    const uint32_t a_base = sb
        + (uint32_t)((mwarp * 16 + (lane & 15)) * PA + ((lane >> 4) << 2)) * 4u;
    const uint32_t b_lane =
        (uint32_t)((nwarp * 32 + (lane & 7)) * PB + (((lane >> 3) & 1) << 2)) * 4u;

    produce_prep(Bmat, sb, mb, tid, 0);
    produce_prep(Bmat, sb, mb, tid, 1);
    produce_prep(Bmat, sb, mb, tid, 2);

    #pragma unroll 1
    for (int c = 0; c < NCH; ++c) {
        int cp = c + 3;
        if (cp < NCH) {
            int q2 = cp >> 2;
            if (q2 >= 1)
                MBAR_WAIT(mbe + (uint32_t)(cp & 3) * 8u, (q2 - 1) & 1);
            produce_prep(Bmat, sb, mb, tid, cp);
        }
        MBAR_WAIT(mb + (uint32_t)(c & 3) * 8u, (c >> 2) & 1);

        const uint32_t a_c = a_base + (uint32_t)c * 64u;
        const uint32_t b_c = sb + (uint32_t)(AF1 + (c & 3) * BSTG) * 4u + b_lane;
        #pragma unroll
        for (int ks = 0; ks < 2; ++ks) {
            uint32_t afr[4];
            ldsm_x4(afr, a_c + ks * 32u);
            uint32_t bfr[4][2];
            #pragma unroll
            for (int nt = 0; nt < 4; ++nt)
                ldsm_x2(bfr[nt], b_c + (uint32_t)nt * (8u * PB * 4u) + ks * 32u);
            #pragma unroll
            for (int nt = 0; nt < 4; ++nt)
                mma_tf32(acc[nt], afr, bfr[nt]);
        }
        MBAR_ARRIVE(mbe + (uint32_t)(c & 3) * 8u);
    }

    #pragma unroll
    for (int r2 = 0; r2 < 2; ++r2) {
        int row = row0 + mwarp * 16 + grp + r2 * 8;
        #pragma unroll
        for (int nt = 0; nt < 4; ++nt) {
            int col = nwarp * 32 + nt * 8 + tig * 2;
            float2 bv = *reinterpret_cast<const float2*>(sm + XF1 + col);
            float2 o  = make_float2(acc[nt][r2 * 2 + 0] + bv.x,
                                    acc[nt][r2 * 2 + 1] + bv.y);
            *reinterpret_cast<float2*>(outp + (size_t)row * E_ + col) = o;
        }
    }

    __threadfence();
    __syncthreads();
    if (tid == 0) atomicAdd(&g_prep_done, 1u);
}

// ======================= fused kernel ======================================
__global__ void __launch_bounds__(512, 1)
memcell_fused(const float* __restrict__ state, const float* __restrict__ U,
              const float* __restrict__ x, const float* __restrict__ keys,
              const float* __restrict__ V, const float* __restrict__ W,
              const float* __restrict__ bias, float* __restrict__ out)
{
    extern __shared__ float sm[];
    if (blockIdx.x < NC1) {
        // convert 2 rows of U to fp16 (covered by prep counter + fence)
        size_t o = (size_t)blockIdx.x * 512 + threadIdx.x;
        g_Uh[o] = __float2half_rn(U[o]);
        prep_body(x, W, bias, g_c1, blockIdx.x * 32, sm);
    } else if (blockIdx.x == NC1) {
        prep_body(keys, V, g_zero, g_c2, 0, sm);
    } else {
        main_body(state, x, keys, out, sm, blockIdx.x - NPREP);
    }
}

// ===========================================================================
extern "C" void kernel_launch(void* const* d_in, const int* in_sizes, int n_in,
                              void* d_out, int out_size)
{
    const float* x     = (const float*)d_in[0];
    const float* state = (const float*)d_in[1];
    const float* keys  = (const float*)d_in[2];
    const float* U     = (const float*)d_in[3];
    const float* V     = (const float*)d_in[4];
    const float* W     = (const float*)d_in[5];
    const float* bias  = (const float*)d_in[6];
    float* out = (float*)d_out;

    cudaFuncSetAttribute(memcell_fused,
                         cudaFuncAttributeMaxDynamicSharedMemorySize, MAIN_SMEM);

    memcell_fused<<<NPREP + NMAIN, 512, MAIN_SMEM>>>(state, U, x, keys,
                                                     V, W, bias, out);
}

// round 14
// speedup vs baseline: 1.1601x; 1.1601x over previous
#include <cuda_runtime.h>
#include <cuda_fp16.h>
#include <math.h>
#include <stdint.h>

#define B_   4096
#define J_   32
#define E_   256
#define ROWS (B_ * J_)
#define NC1   (B_ / 32)              // 128 c1 CTAs (M=32 each)
#define NPREP (NC1 + 1)              // + 1 c2 CTA
#define NMAIN (ROWS / 128)           // 1024 main CTAs

// ======================= scratch (device globals) ==========================
__device__ float  g_c1[B_ * E_];         // bias + x @ W^T
__device__ float  g_c2[J_ * E_];         // keys @ V^T
__device__ float  g_zero[E_];            // zero "bias" for the c2 CTA
__device__ __half g_Uh[E_ * E_];         // U converted to fp16 (by prep)
__device__ unsigned int g_prep_done;
__device__ unsigned int g_main_done;

// ======================= PTX helpers =======================================
__device__ __forceinline__ uint32_t smem_u32(const void* p) {
    uint32_t a;
    asm("{ .reg .u64 t; cvta.to.shared.u64 t, %1; cvt.u32.u64 %0, t; }"
        : "=r"(a) : "l"(p));
    return a;
}

#define CP_ASYNC16(dst, src)                                                  \
    asm volatile("cp.async.cg.shared.global [%0], [%1], 16;"                  \
        :: "r"(dst), "l"(__cvta_generic_to_global((const void*)(src))) : "memory")

#define MBAR_INIT(addr, cnt)                                                  \
    asm volatile("mbarrier.init.shared.b64 [%0], %1;" :: "r"(addr), "r"(cnt) : "memory")
#define CP_MBAR_ARRIVE(addr)                                                  \
    asm volatile("cp.async.mbarrier.arrive.noinc.shared.b64 [%0];"            \
        :: "r"(addr) : "memory")
#define MBAR_ARRIVE(addr)                                                     \
    asm volatile("mbarrier.arrive.shared.b64 _, [%0];" :: "r"(addr) : "memory")
#define MBAR_WAIT(addr, parity) do {                                          \
    asm volatile("{\n\t.reg .pred P;\n\t"                                     \
        "WL_%=:\n\t"                                                          \
        "mbarrier.try_wait.parity.shared.b64 P, [%0], %1;\n\t"                \
        "@P bra.uni WD_%=;\n\t"                                               \
        "bra.uni WL_%=;\n\t"                                                  \
        "WD_%=:\n\t}"                                                         \
        :: "r"(addr), "r"(parity) : "memory");                                \
} while (0)

__device__ __forceinline__ void mma_tf32(float* d, const uint32_t* a,
                                         const uint32_t* b) {
    asm volatile(
        "mma.sync.aligned.m16n8k8.row.col.f32.tf32.tf32.f32 "
        "{%0,%1,%2,%3}, {%4,%5,%6,%7}, {%8,%9}, {%0,%1,%2,%3};"
        : "+f"(d[0]), "+f"(d[1]), "+f"(d[2]), "+f"(d[3])
        : "r"(a[0]), "r"(a[1]), "r"(a[2]), "r"(a[3]), "r"(b[0]), "r"(b[1]));
}
__device__ __forceinline__ void mma_f16(float* d, const uint32_t* a,
                                        const uint32_t* b) {
    asm volatile(
        "mma.sync.aligned.m16n8k16.row.col.f32.f16.f16.f32 "
        "{%0,%1,%2,%3}, {%4,%5,%6,%7}, {%8,%9}, {%0,%1,%2,%3};"
        : "+f"(d[0]), "+f"(d[1]), "+f"(d[2]), "+f"(d[3])
        : "r"(a[0]), "r"(a[1]), "r"(a[2]), "r"(a[3]), "r"(b[0]), "r"(b[1]));
}

__device__ __forceinline__ void ldsm_x4(uint32_t* r, uint32_t addr) {
    asm volatile("ldmatrix.sync.aligned.m8n8.x4.shared.b16 {%0,%1,%2,%3}, [%4];"
        : "=r"(r[0]), "=r"(r[1]), "=r"(r[2]), "=r"(r[3]) : "r"(addr));
}
__device__ __forceinline__ void ldsm_x2(uint32_t* r, uint32_t addr) {
    asm volatile("ldmatrix.sync.aligned.m8n8.x2.shared.b16 {%0,%1}, [%2];"
        : "=r"(r[0]), "=r"(r[1]) : "r"(addr));
}

// ======================= smem layout =======================================
#define NCH   16                     // K chunks of 16
// ---- main CTA (fp16, 256 thr / 8 warps, warp tile 64x64) ----
#define PAHB  528                    // A fp16 row pitch bytes (264 halves)
#define PBHB  48                     // B fp16 row pitch bytes (24 halves)
#define BSTGB 12288                  // bytes per B stage (256*48)
#define AH_B  0                      // A fp16 tile base (byte offset)
#define BF_F  16896                  // float ofs of B stages (A = 128*528B)
#define XF_F  29184                  // x tile (4x256 fp32)
#define GF_F  30208                  // gate[128]
#define RED_F 30336                  // norm red[128*4]
#define INV_F 30848                  // inv[128]
#define MBR_F 30976                  // 8 mbarriers
#define SMEMF (MBR_F + 16)           // 30992 floats
#define MAIN_SMEM (SMEMF * 4)        // 123,968 bytes
// ---- prep CTA (tf32, R10-proven 256-thr layout) ----
#define PA    260
#define PB    20
#define BSTG  5120
#define AF1   8320
#define XF1   (AF1 + 4 * BSTG)       // 28800
#define MB1F  (XF1 + 256)            // 29056  (< SMEMF ✓)

__device__ __forceinline__ void init_ring(uint32_t mb, int tid, int cnt)
{
    if (tid == 0) {
        #pragma unroll
        for (int s = 0; s < 4; ++s) {
            MBAR_INIT(mb + s * 8u, cnt);
            MBAR_INIT(mb + 32u + s * 8u, cnt);
        }
    }
    __syncthreads();
}

// ======================= main-CTA body (fp16, 8 warps) =====================
// B producer: chunk p of g_Uh (k local to stage); 2 cp.async(16B)/thread.
__device__ __forceinline__ void produce_h(uint32_t sb, uint32_t mb,
                                          int tid, int p)
{
    uint32_t bst = sb + (uint32_t)BF_F * 4u + (uint32_t)(p & 3) * BSTGB;
    #pragma unroll
    for (int i = 0; i < 2; ++i) {
        int idx = tid + (i << 8);
        int f = idx >> 1, hf = idx & 1;
        CP_ASYNC16(bst + (uint32_t)(f * PBHB + hf * 16),
                   (const __half*)g_Uh + (size_t)f * E_ + p * 16 + hf * 8);
    }
    CP_MBAR_ARRIVE(mb + (uint32_t)(p & 3) * 8u);
}

__device__ void main_body(const float* __restrict__ state,
                          const float* __restrict__ x,
                          const float* __restrict__ keys,
                          float* __restrict__ out,
                          float* sm, int bid)
{
    const int tid  = threadIdx.x;
    const int lane = tid & 31;
    const int wid  = tid >> 5;
    const int grp  = lane >> 2;
    const int tig  = lane & 3;
    const int mwarp = wid >> 2;       // 0..1 (64 rows each)
    const int nwarp = wid & 3;        // 0..3 (64 cols each)
    const int row0 = bid * 128;
    const uint32_t sb = smem_u32(sm);
    const uint32_t mb  = sb + (uint32_t)MBR_F * 4u;
    const uint32_t mbe = mb + 32u;
    char* smc = reinterpret_cast<char*>(sm);

    init_ring(mb, tid, 256);

    // ---- stage x (4 rows x 256 fp32) ----
    if (tid < 256)
        reinterpret_cast<float4*>(sm + XF_F)[tid] =
            reinterpret_cast<const float4*>(x + (size_t)(row0 >> 5) * E_)[tid];

    // ---- A staging: LDG state fp32 -> cvt rn -> STS fp16 (no extras) ----
    #pragma unroll 4
    for (int i = 0; i < 32; ++i) {
        int idx = tid + (i << 8);
        int r = idx >> 6, c4 = idx & 63;
        float4 sv = reinterpret_cast<const float4*>(
                        state + (size_t)(row0 + r) * E_)[c4];
        __half2 h0 = __floats2half2_rn(sv.x, sv.y);
        __half2 h1 = __floats2half2_rn(sv.z, sv.w);
        uint2 u; u.x = *(uint32_t*)&h0; u.y = *(uint32_t*)&h1;
        *reinterpret_cast<uint2*>(smc + AH_B + r * PAHB + c4 * 8) = u;
    }
    __syncthreads();

    // ---- wait prep (needs g_Uh before the B ring) ----
    if (tid == 0)
        while (atomicAdd(&g_prep_done, 0u) < (unsigned)NPREP) {}
    __syncthreads();

    float acc[4][8][4];
    #pragma unroll
    for (int mt = 0; mt < 4; ++mt)
        #pragma unroll
        for (int nt = 0; nt < 8; ++nt)
            #pragma unroll
            for (int q = 0; q < 4; ++q) acc[mt][nt][q] = 0.f;

    // ldmatrix lane-address bases (bytes) -- R13-proven mappings
    const uint32_t a_base = sb + AH_B
        + (uint32_t)((mwarp * 64 + (lane & 15)) * PAHB + ((lane >> 4) << 4));
    const uint32_t b_lane =
        (uint32_t)((nwarp * 64 + (lane & 7)) * PBHB + (((lane >> 3) & 1) << 4));

    produce_h(sb, mb, tid, 0);
    produce_h(sb, mb, tid, 1);
    produce_h(sb, mb, tid, 2);

    #pragma unroll 1
    for (int c = 0; c < NCH; ++c) {
        int cp = c + 3;
        if (cp < NCH) {
            int q2 = cp >> 2;
            if (q2 >= 1)
                MBAR_WAIT(mbe + (uint32_t)(cp & 3) * 8u, (q2 - 1) & 1);
            produce_h(sb, mb, tid, cp);
        }
        MBAR_WAIT(mb + (uint32_t)(c & 3) * 8u, (c >> 2) & 1);

        const uint32_t a_c = a_base + (uint32_t)c * 32u;       // A: global k
        const uint32_t b_c = sb + (uint32_t)BF_F * 4u
                           + (uint32_t)(c & 3) * BSTGB + b_lane;
        uint32_t afr[4][4];
        #pragma unroll
        for (int mt = 0; mt < 4; ++mt)
            ldsm_x4(afr[mt], a_c + (uint32_t)mt * (16u * PAHB));
        uint32_t bfr[8][2];
        #pragma unroll
        for (int nt = 0; nt < 8; ++nt)
            ldsm_x2(bfr[nt], b_c + (uint32_t)nt * (8u * PBHB));
        #pragma unroll
        for (int nt = 0; nt < 8; ++nt) {
            #pragma unroll
            for (int mt = 0; mt < 4; ++mt)
                mma_f16(acc[mt][nt], afr[mt], bfr[nt]);
        }
        MBAR_ARRIVE(mbe + (uint32_t)(c & 3) * 8u);
    }

    __syncthreads();   // all warps out of the mainloop

    // ---- stage keys (32x256 fp32, pitch 260) into the dead B area ----
    #pragma unroll
    for (int i = 0; i < 8; ++i) {
        int idx = tid + (i << 8);
        int r = idx >> 6, c4 = idx & 63;
        *reinterpret_cast<float4*>(sm + BF_F + r * PA + c4 * 4) =
            reinterpret_cast<const float4*>(keys + (size_t)r * E_)[c4];
    }
    __syncthreads();

    // ---- gate: sigma( x.(s+key) ); s from GLOBAL fp32 (L2-hot); 4thr/row --
    #pragma unroll
    for (int rr = 0; rr < 2; ++rr) {
        int r = (tid >> 2) + rr * 64, q = tid & 3;
        const float* srow = state + (size_t)(row0 + r) * E_;
        const float* krow = sm + BF_F + (r & 31) * PA;
        const float* xrow = sm + XF_F + (r >> 5) * 256;
        float dot = 0.f;
        #pragma unroll
        for (int u = 0; u < 16; ++u) {
            int f4 = u * 4 + q;
            float4 av = reinterpret_cast<const float4*>(srow)[f4];
            float4 kv = *reinterpret_cast<const float4*>(krow + f4 * 4);
            float4 xv = *reinterpret_cast<const float4*>(xrow + f4 * 4);
            dot += (av.x + kv.x) * xv.x + (av.y + kv.y) * xv.y
                 + (av.z + kv.z) * xv.z + (av.w + kv.w) * xv.w;
        }
        dot += __shfl_xor_sync(0xffffffffu, dot, 1);
        dot += __shfl_xor_sync(0xffffffffu, dot, 2);
        if (q == 0)
            sm[GF_F + r] = 1.f / (1.f + expf(-dot));
    }
    __syncthreads();

    // ---- epilogue pass 1: v = s + g*relu(acc + c1 + c2) -> Ah (fp16) ----
    float* red = sm + RED_F;
    float* inv = sm + INV_F;
    #pragma unroll
    for (int mt = 0; mt < 4; ++mt) {
        #pragma unroll
        for (int r2 = 0; r2 < 2; ++r2) {
            int rl   = mwarp * 64 + mt * 16 + grp + r2 * 8;
            int grow = row0 + rl;
            float gv = sm[GF_F + rl];
            const float* c1r = g_c1 + (size_t)(grow >> 5) * E_;
            const float* c2r = g_c2 + (size_t)(grow & 31) * E_;
            float ss = 0.f;
            #pragma unroll
            for (int nt = 0; nt < 8; ++nt) {
                int col = nwarp * 64 + nt * 8 + tig * 2;
                uint32_t su = *reinterpret_cast<uint32_t*>(
                                  smc + AH_B + rl * PAHB + col * 2);
                float2 svv = __half22float2(*reinterpret_cast<__half2*>(&su));
                float2 c1v = *reinterpret_cast<const float2*>(c1r + col);
                float2 c2v = *reinterpret_cast<const float2*>(c2r + col);
                float d0 = acc[mt][nt][r2 * 2 + 0] + c1v.x + c2v.x;
                float d1 = acc[mt][nt][r2 * 2 + 1] + c1v.y + c2v.y;
                float v0 = svv.x + gv * fmaxf(d0, 0.f);
                float v1 = svv.y + gv * fmaxf(d1, 0.f);
                ss += v0 * v0 + v1 * v1;
                __half2 hv = __floats2half2_rn(v0, v1);
                *reinterpret_cast<uint32_t*>(smc + AH_B + rl * PAHB + col * 2)
                    = *(uint32_t*)&hv;
            }
            ss += __shfl_xor_sync(0xffffffffu, ss, 1);
            ss += __shfl_xor_sync(0xffffffffu, ss, 2);
            if (tig == 0) red[rl * 4 + nwarp] = ss;
        }
    }
    __syncthreads();
    if (tid < 128) {
        float s = red[tid * 4] + red[tid * 4 + 1]
                + red[tid * 4 + 2] + red[tid * 4 + 3];
        inv[tid] = 1.f / (sqrtf(s) + 1e-8f);
    }
    __syncthreads();

    // ---- epilogue pass 2: coalesced normalized writeback (fp16 -> fp32) ---
    #pragma unroll
    for (int i = 0; i < 16; ++i) {
        int idx = tid + (i << 8);
        int r = idx >> 5, c8 = idx & 31;
        float iv = inv[r];
        uint4 u = *reinterpret_cast<uint4*>(smc + AH_B + r * PAHB + c8 * 16);
        const __half2* hp = reinterpret_cast<const __half2*>(&u);
        float2 f0 = __half22float2(hp[0]), f1 = __half22float2(hp[1]);
        float2 f2 = __half22float2(hp[2]), f3 = __half22float2(hp[3]);
        float4 o0 = make_float4(f0.x * iv, f0.y * iv, f1.x * iv, f1.y * iv);
        float4 o1 = make_float4(f2.x * iv, f2.y * iv, f3.x * iv, f3.y * iv);
        float4* op = reinterpret_cast<float4*>(out + (size_t)(row0 + r) * E_
                                               + c8 * 8);
        op[0] = o0; op[1] = o1;
    }

    // ---- last main CTA resets the handshake counters ----
    __syncthreads();
    if (tid == 0) {
        unsigned v = atomicAdd(&g_main_done, 1u);
        if (v == (unsigned)(NMAIN - 1)) {
            atomicExch(&g_prep_done, 0u);
            atomicExch(&g_main_done, 0u);
        }
    }
}

// ======================= prep-CTA body (tf32 M=32, 256 thr, R10-proven) ====
__device__ __forceinline__ void produce_prep(const float* __restrict__ Bg,
                                             uint32_t sb, uint32_t mb,
                                             int tid, int p)
{
    uint32_t bst = sb + (uint32_t)(AF1 + (p & 3) * BSTG) * 4u;
    #pragma unroll
    for (int i = 0; i < 4; ++i) {
        int idx = tid + (i << 8);
        int f = idx >> 2, k4 = idx & 3;
        CP_ASYNC16(bst + (uint32_t)(f * PB + k4 * 4) * 4u,
                   Bg + (size_t)f * E_ + p * 16 + k4 * 4);
    }
    CP_MBAR_ARRIVE(mb + (uint32_t)(p & 3) * 8u);
}

__device__ void prep_body(const float* __restrict__ A,
                          const float* __restrict__ Bmat,
                          const float* __restrict__ bias,
                          float* __restrict__ outp, int row0,
                          float* sm)
{
    const int tid  = threadIdx.x;
    const int lane = tid & 31;
    const int wid  = tid >> 5;
    const int grp  = lane >> 2;
    const int tig  = lane & 3;
    const int mwarp = wid >> 2;       // 0..1 (16 rows each)
    const int nwarp = wid & 3;        // 0..3 (64 cols each)
    const uint32_t sb = smem_u32(sm);
    const uint32_t mb  = sb + (uint32_t)MB1F * 4u;
    const uint32_t mbe = mb + 32u;

    init_ring(mb, tid, 256);

    #pragma unroll
    for (int i = 0; i < 8; ++i) {
        int idx = tid + (i << 8);
        int r = idx >> 6, c4 = idx & 63;
        CP_ASYNC16(sb + (uint32_t)(r * PA + c4 * 4) * 4u,
                   A + (size_t)(row0 + r) * E_ + c4 * 4);
    }
    if (tid < 64)
        CP_ASYNC16(sb + (uint32_t)(XF1 + tid * 4) * 4u, bias + tid * 4);

    float acc[8][4];
    #pragma unroll
    for (int nt = 0; nt < 8; ++nt)
        #pragma unroll
        for (int q = 0; q < 4; ++q) acc[nt][q] = 0.f;

    const uint32_t a_base = sb
        + (uint32_t)((mwarp * 16 + (lane & 15)) * PA + ((lane >> 4) << 2)) * 4u;
    const uint32_t b_lane =
        (uint32_t)((nwarp * 64 + (lane & 7)) * PB + (((lane >> 3) & 1) << 2)) * 4u;

    produce_prep(Bmat, sb, mb, tid, 0);
    produce_prep(Bmat, sb, mb, tid, 1);
    produce_prep(Bmat, sb, mb, tid, 2);

    #pragma unroll 1
    for (int c = 0; c < NCH; ++c) {
        int cp = c + 3;
        if (cp < NCH) {
            int q2 = cp >> 2;
            if (q2 >= 1)
                MBAR_WAIT(mbe + (uint32_t)(cp & 3) * 8u, (q2 - 1) & 1);
            produce_prep(Bmat, sb, mb, tid, cp);
        }
        MBAR_WAIT(mb + (uint32_t)(c & 3) * 8u, (c >> 2) & 1);

        const uint32_t a_c = a_base + (uint32_t)c * 64u;
        const uint32_t b_c = sb + (uint32_t)(AF1 + (c & 3) * BSTG) * 4u + b_lane;
        #pragma unroll
        for (int ks = 0; ks < 2; ++ks) {
            uint32_t afr[4];
            ldsm_x4(afr, a_c + ks * 32u);
            uint32_t bfr[8][2];
            #pragma unroll
            for (int nt = 0; nt < 8; ++nt)
                ldsm_x2(bfr[nt], b_c + (uint32_t)nt * (8u * PB * 4u) + ks * 32u);
            #pragma unroll
            for (int nt = 0; nt < 8; ++nt)
                mma_tf32(acc[nt], afr, bfr[nt]);
        }
        MBAR_ARRIVE(mbe + (uint32_t)(c & 3) * 8u);
    }

    #pragma unroll
    for (int r2 = 0; r2 < 2; ++r2) {
        int row = row0 + mwarp * 16 + grp + r2 * 8;
        #pragma unroll
        for (int nt = 0; nt < 8; ++nt) {
            int col = nwarp * 64 + nt * 8 + tig * 2;
            float2 bv = *reinterpret_cast<const float2*>(sm + XF1 + col);
            float2 o  = make_float2(acc[nt][r2 * 2 + 0] + bv.x,
                                    acc[nt][r2 * 2 + 1] + bv.y);
            *reinterpret_cast<float2*>(outp + (size_t)row * E_ + col) = o;
        }
    }

    __threadfence();
    __syncthreads();
    if (tid == 0) atomicAdd(&g_prep_done, 1u);
}

// ======================= fused kernel ======================================
__global__ void __launch_bounds__(256, 1)
memcell_fused(const float* __restrict__ state, const float* __restrict__ U,
              const float* __restrict__ x, const float* __restrict__ keys,
              const float* __restrict__ V, const float* __restrict__ W,
              const float* __restrict__ bias, float* __restrict__ out)
{
    extern __shared__ float sm[];
    if (blockIdx.x < NC1) {
        // convert 2x256 halves of U to fp16 (covered by prep counter+fence)
        #pragma unroll
        for (int i = 0; i < 2; ++i) {
            size_t o = (size_t)blockIdx.x * 512 + threadIdx.x + i * 256;
            g_Uh[o] = __float2half_rn(U[o]);
        }
        prep_body(x, W, bias, g_c1, blockIdx.x * 32, sm);
    } else if (blockIdx.x == NC1) {
        prep_body(keys, V, g_zero, g_c2, 0, sm);
    } else {
        main_body(state, x, keys, out, sm, blockIdx.x - NPREP);
    }
}

// ===========================================================================
extern "C" void kernel_launch(void* const* d_in, const int* in_sizes, int n_in,
                              void* d_out, int out_size)
{
    const float* x     = (const float*)d_in[0];
    const float* state = (const float*)d_in[1];
    const float* keys  = (const float*)d_in[2];
    const float* U     = (const float*)d_in[3];
    const float* V     = (const float*)d_in[4];
    const float* W     = (const float*)d_in[5];
    const float* bias  = (const float*)d_in[6];
    float* out = (float*)d_out;

    cudaFuncSetAttribute(memcell_fused,
                         cudaFuncAttributeMaxDynamicSharedMemorySize, MAIN_SMEM);

    memcell_fused<<<NPREP + NMAIN, 256, MAIN_SMEM>>>(state, U, x, keys,
                                                     V, W, bias, out);
}

// round 16
// speedup vs baseline: 1.1822x; 1.0191x over previous
#include <cuda_runtime.h>
#include <cuda_fp16.h>
#include <math.h>
#include <stdint.h>

#define B_   4096
#define J_   32
#define E_   256
#define ROWS (B_ * J_)
#define NC1   (B_ / 32)              // 128 c1 CTAs (M=32 each)
#define NPREP (NC1 + 1)              // + 1 c2 CTA
#define NMAIN (ROWS / 128)           // 1024 main CTAs

// ======================= scratch (device globals) ==========================
__device__ float  g_c1[B_ * E_];         // bias + x @ W^T
__device__ float  g_c2[J_ * E_];         // keys @ V^T
__device__ float  g_zero[E_];            // zero "bias" for the c2 CTA
__device__ __half g_Uh[E_ * E_];         // U converted to fp16 (by prep)
__device__ unsigned int g_prep_done;
__device__ unsigned int g_main_done;

// ======================= PTX helpers =======================================
__device__ __forceinline__ uint32_t smem_u32(const void* p) {
    uint32_t a;
    asm("{ .reg .u64 t; cvta.to.shared.u64 t, %1; cvt.u32.u64 %0, t; }"
        : "=r"(a) : "l"(p));
    return a;
}

#define CP_ASYNC16(dst, src)                                                  \
    asm volatile("cp.async.cg.shared.global [%0], [%1], 16;"                  \
        :: "r"(dst), "l"(__cvta_generic_to_global((const void*)(src))) : "memory")
#define CP_COMMIT() asm volatile("cp.async.commit_group;" ::: "memory")
#define CP_WAIT0()  asm volatile("cp.async.wait_group 0;" ::: "memory")

#define MBAR_INIT(addr, cnt)                                                  \
    asm volatile("mbarrier.init.shared.b64 [%0], %1;" :: "r"(addr), "r"(cnt) : "memory")
#define CP_MBAR_ARRIVE(addr)                                                  \
    asm volatile("cp.async.mbarrier.arrive.noinc.shared.b64 [%0];"            \
        :: "r"(addr) : "memory")
#define MBAR_ARRIVE(addr)                                                     \
    asm volatile("mbarrier.arrive.shared.b64 _, [%0];" :: "r"(addr) : "memory")
#define MBAR_WAIT(addr, parity) do {                                          \
    asm volatile("{\n\t.reg .pred P;\n\t"                                     \
        "WL_%=:\n\t"                                                          \
        "mbarrier.try_wait.parity.shared.b64 P, [%0], %1;\n\t"                \
        "@P bra.uni WD_%=;\n\t"                                               \
        "bra.uni WL_%=;\n\t"                                                  \
        "WD_%=:\n\t}"                                                         \
        :: "r"(addr), "r"(parity) : "memory");                                \
} while (0)

__device__ __forceinline__ void mma_tf32(float* d, const uint32_t* a,
                                         const uint32_t* b) {
    asm volatile(
        "mma.sync.aligned.m16n8k8.row.col.f32.tf32.tf32.f32 "
        "{%0,%1,%2,%3}, {%4,%5,%6,%7}, {%8,%9}, {%0,%1,%2,%3};"
        : "+f"(d[0]), "+f"(d[1]), "+f"(d[2]), "+f"(d[3])
        : "r"(a[0]), "r"(a[1]), "r"(a[2]), "r"(a[3]), "r"(b[0]), "r"(b[1]));
}
__device__ __forceinline__ void mma_f16(float* d, const uint32_t* a,
                                        const uint32_t* b) {
    asm volatile(
        "mma.sync.aligned.m16n8k16.row.col.f32.f16.f16.f32 "
        "{%0,%1,%2,%3}, {%4,%5,%6,%7}, {%8,%9}, {%0,%1,%2,%3};"
        : "+f"(d[0]), "+f"(d[1]), "+f"(d[2]), "+f"(d[3])
        : "r"(a[0]), "r"(a[1]), "r"(a[2]), "r"(a[3]), "r"(b[0]), "r"(b[1]));
}

__device__ __forceinline__ void ldsm_x4(uint32_t* r, uint32_t addr) {
    asm volatile("ldmatrix.sync.aligned.m8n8.x4.shared.b16 {%0,%1,%2,%3}, [%4];"
        : "=r"(r[0]), "=r"(r[1]), "=r"(r[2]), "=r"(r[3]) : "r"(addr));
}
__device__ __forceinline__ void ldsm_x2(uint32_t* r, uint32_t addr) {
    asm volatile("ldmatrix.sync.aligned.m8n8.x2.shared.b16 {%0,%1}, [%2];"
        : "=r"(r[0]), "=r"(r[1]) : "r"(addr));
}

// ======================= smem layout =======================================
#define NCH   16                     // K chunks of 16
// ---- main CTA (fp16, 256 thr / 8 warps, warp tile 64x64, NO ring) ----
#define PHB   528                    // fp16 row pitch bytes (264 halves)
#define UH_B  0                      // U fp16 tile: 256 x 528B = 135,168
#define AH_B  135168                 // A fp16 tile: 128 x 528B = 67,584
#define XF_F  50688                  // x tile (4x256 fp32), float offset
#define GF_F  51712                  // gate[128]
#define RED_F 51840                  // norm red[128*4]
#define INV_F 52352                  // inv[128]
#define SMEMF 52480                  // floats
#define MAIN_SMEM (SMEMF * 4)        // 209,920 bytes
// ---- prep CTA (tf32, R10-proven 256-thr layout) ----
#define PA    260
#define PB    20
#define BSTG  5120
#define AF1   8320
#define XF1   (AF1 + 4 * BSTG)       // 28800
#define MB1F  (XF1 + 256)            // 29056  (< SMEMF ✓)

__device__ __forceinline__ void init_ring(uint32_t mb, int tid, int cnt)
{
    if (tid == 0) {
        #pragma unroll
        for (int s = 0; s < 4; ++s) {
            MBAR_INIT(mb + s * 8u, cnt);
            MBAR_INIT(mb + 32u + s * 8u, cnt);
        }
    }
    __syncthreads();
}

// ======================= main-CTA body (fp16, resident U, no ring) =========
__device__ void main_body(const float* __restrict__ state,
                          const float* __restrict__ x,
                          const float* __restrict__ keys,
                          float* __restrict__ out,
                          float* sm, int bid)
{
    const int tid  = threadIdx.x;
    const int lane = tid & 31;
    const int wid  = tid >> 5;
    const int grp  = lane >> 2;
    const int tig  = lane & 3;
    const int mwarp = wid >> 2;       // 0..1 (64 rows each)
    const int nwarp = wid & 3;        // 0..3 (64 cols each)
    const int row0 = bid * 128;
    const uint32_t sb = smem_u32(sm);
    char* smc = reinterpret_cast<char*>(sm);

    // ---- stage x (4 rows x 256 fp32) ----
    if (tid < 256)
        reinterpret_cast<float4*>(sm + XF_F)[tid] =
            reinterpret_cast<const float4*>(x + (size_t)(row0 >> 5) * E_)[tid];

    // ---- A staging: LDG state fp32 -> cvt rn -> STS fp16 ----
    #pragma unroll 4
    for (int i = 0; i < 32; ++i) {
        int idx = tid + (i << 8);
        int r = idx >> 6, c4 = idx & 63;
        float4 sv = reinterpret_cast<const float4*>(
                        state + (size_t)(row0 + r) * E_)[c4];
        __half2 h0 = __floats2half2_rn(sv.x, sv.y);
        __half2 h1 = __floats2half2_rn(sv.z, sv.w);
        uint2 u; u.x = *(uint32_t*)&h0; u.y = *(uint32_t*)&h1;
        *reinterpret_cast<uint2*>(smc + AH_B + r * PHB + c4 * 8) = u;
    }

    // ---- wait prep (needs g_Uh) ----
    if (tid == 0)
        while (atomicAdd(&g_prep_done, 0u) < (unsigned)NPREP) {}
    __syncthreads();

    // ---- stage U fp16 (256 rows x 256 halves): 8192 x 16B, 32 per thread --
    // idx in [0, 8192): row f = idx>>5, 16B chunk c16 = idx&31.
    #pragma unroll
    for (int i = 0; i < 32; ++i) {
        int idx = tid + (i << 8);
        int f = idx >> 5, c16 = idx & 31;
        CP_ASYNC16(sb + (uint32_t)(UH_B + f * PHB + c16 * 16),
                   (const __half*)g_Uh + (size_t)f * E_ + c16 * 8);
    }
    CP_COMMIT();
    CP_WAIT0();
    __syncthreads();

    float acc[4][8][4];
    #pragma unroll
    for (int mt = 0; mt < 4; ++mt)
        #pragma unroll
        for (int nt = 0; nt < 8; ++nt)
            #pragma unroll
            for (int q = 0; q < 4; ++q) acc[mt][nt][q] = 0.f;

    // ldmatrix lane-address bases (bytes) -- R13/R14-proven mappings
    const uint32_t a_base = sb + AH_B
        + (uint32_t)((mwarp * 64 + (lane & 15)) * PHB + ((lane >> 4) << 4));
    const uint32_t b_base = sb + UH_B
        + (uint32_t)((nwarp * 64 + (lane & 7)) * PHB + (((lane >> 3) & 1) << 4));

    // ---- mainloop: straight-line, fully resident, zero synchronization ----
    #pragma unroll 2
    for (int c = 0; c < NCH; ++c) {
        const uint32_t a_c = a_base + (uint32_t)c * 32u;
        const uint32_t b_c = b_base + (uint32_t)c * 32u;
        uint32_t afr[4][4];
        #pragma unroll
        for (int mt = 0; mt < 4; ++mt)
            ldsm_x4(afr[mt], a_c + (uint32_t)mt * (16u * PHB));
        uint32_t bfr[8][2];
        #pragma unroll
        for (int nt = 0; nt < 8; ++nt)
            ldsm_x2(bfr[nt], b_c + (uint32_t)nt * (8u * PHB));
        #pragma unroll
        for (int nt = 0; nt < 8; ++nt) {
            #pragma unroll
            for (int mt = 0; mt < 4; ++mt)
                mma_f16(acc[mt][nt], afr[mt], bfr[nt]);
        }
    }

    // ---- gate: sigma( x.(s+key) ); s,key from global fp32 (L2-hot) ----
    #pragma unroll
    for (int rr = 0; rr < 2; ++rr) {
        int r = (tid >> 2) + rr * 64, q = tid & 3;
        const float* srow = state + (size_t)(row0 + r) * E_;
        const float* krow = keys + (size_t)(r & 31) * E_;
        const float* xrow = sm + XF_F + (r >> 5) * 256;
        float dot = 0.f;
        #pragma unroll
        for (int u = 0; u < 16; ++u) {
            int f4 = u * 4 + q;
            float4 av = reinterpret_cast<const float4*>(srow)[f4];
            float4 kv = reinterpret_cast<const float4*>(krow)[f4];
            float4 xv = *reinterpret_cast<const float4*>(xrow + f4 * 4);
            dot += (av.x + kv.x) * xv.x + (av.y + kv.y) * xv.y
                 + (av.z + kv.z) * xv.z + (av.w + kv.w) * xv.w;
        }
        dot += __shfl_xor_sync(0xffffffffu, dot, 1);
        dot += __shfl_xor_sync(0xffffffffu, dot, 2);
        if (q == 0)
            sm[GF_F + r] = 1.f / (1.f + expf(-dot));
    }
    __syncthreads();

    // ---- epilogue pass 1: v = s + g*relu(acc + c1 + c2) -> Ah (fp16) ----
    float* red = sm + RED_F;
    float* inv = sm + INV_F;
    #pragma unroll
    for (int mt = 0; mt < 4; ++mt) {
        #pragma unroll
        for (int r2 = 0; r2 < 2; ++r2) {
            int rl   = mwarp * 64 + mt * 16 + grp + r2 * 8;
            int grow = row0 + rl;
            float gv = sm[GF_F + rl];
            const float* c1r = g_c1 + (size_t)(grow >> 5) * E_;
            const float* c2r = g_c2 + (size_t)(grow & 31) * E_;
            float ss = 0.f;
            #pragma unroll
            for (int nt = 0; nt < 8; ++nt) {
                int col = nwarp * 64 + nt * 8 + tig * 2;
                uint32_t su = *reinterpret_cast<uint32_t*>(
                                  smc + AH_B + rl * PHB + col * 2);
                float2 svv = __half22float2(*reinterpret_cast<__half2*>(&su));
                float2 c1v = *reinterpret_cast<const float2*>(c1r + col);
                float2 c2v = *reinterpret_cast<const float2*>(c2r + col);
                float d0 = acc[mt][nt][r2 * 2 + 0] + c1v.x + c2v.x;
                float d1 = acc[mt][nt][r2 * 2 + 1] + c1v.y + c2v.y;
                float v0 = svv.x + gv * fmaxf(d0, 0.f);
                float v1 = svv.y + gv * fmaxf(d1, 0.f);
                ss += v0 * v0 + v1 * v1;
                __half2 hv = __floats2half2_rn(v0, v1);
                *reinterpret_cast<uint32_t*>(smc + AH_B + rl * PHB + col * 2)
                    = *(uint32_t*)&hv;
            }
            ss += __shfl_xor_sync(0xffffffffu, ss, 1);
            ss += __shfl_xor_sync(0xffffffffu, ss, 2);
            if (tig == 0) red[rl * 4 + nwarp] = ss;
        }
    }
    __syncthreads();
    if (tid < 128) {
        float s = red[tid * 4] + red[tid * 4 + 1]
                + red[tid * 4 + 2] + red[tid * 4 + 3];
        inv[tid] = 1.f / (sqrtf(s) + 1e-8f);
    }
    __syncthreads();

    // ---- epilogue pass 2: coalesced normalized writeback (fp16 -> fp32) ---
    #pragma unroll
    for (int i = 0; i < 16; ++i) {
        int idx = tid + (i << 8);
        int r = idx >> 5, c8 = idx & 31;
        float iv = inv[r];
        uint4 u = *reinterpret_cast<uint4*>(smc + AH_B + r * PHB + c8 * 16);
        const __half2* hp = reinterpret_cast<const __half2*>(&u);
        float2 f0 = __half22float2(hp[0]), f1 = __half22float2(hp[1]);
        float2 f2 = __half22float2(hp[2]), f3 = __half22float2(hp[3]);
        float4 o0 = make_float4(f0.x * iv, f0.y * iv, f1.x * iv, f1.y * iv);
        float4 o1 = make_float4(f2.x * iv, f2.y * iv, f3.x * iv, f3.y * iv);
        float4* op = reinterpret_cast<float4*>(out + (size_t)(row0 + r) * E_
                                               + c8 * 8);
        op[0] = o0; op[1] = o1;
    }

    // ---- last main CTA resets the handshake counters ----
    __syncthreads();
    if (tid == 0) {
        unsigned v = atomicAdd(&g_main_done, 1u);
        if (v == (unsigned)(NMAIN - 1)) {
            atomicExch(&g_prep_done, 0u);
            atomicExch(&g_main_done, 0u);
        }
    }
}

// ======================= prep-CTA body (tf32 M=32, 256 thr, proven) ========
__device__ __forceinline__ void produce_prep(const float* __restrict__ Bg,
                                             uint32_t sb, uint32_t mb,
                                             int tid, int p)
{
    uint32_t bst = sb + (uint32_t)(AF1 + (p & 3) * BSTG) * 4u;
    #pragma unroll
    for (int i = 0; i < 4; ++i) {
        int idx = tid + (i << 8);
        int f = idx >> 2, k4 = idx & 3;
        CP_ASYNC16(bst + (uint32_t)(f * PB + k4 * 4) * 4u,
                   Bg + (size_t)f * E_ + p * 16 + k4 * 4);
    }
    CP_MBAR_ARRIVE(mb + (uint32_t)(p & 3) * 8u);
}

__device__ void prep_body(const float* __restrict__ A,
                          const float* __restrict__ Bmat,
                          const float* __restrict__ bias,
                          float* __restrict__ outp, int row0,
                          float* sm)
{
    const int tid  = threadIdx.x;
    const int lane = tid & 31;
    const int wid  = tid >> 5;
    const int grp  = lane >> 2;
    const int tig  = lane & 3;
    const int mwarp = wid >> 2;       // 0..1 (16 rows each)
    const int nwarp = wid & 3;        // 0..3 (64 cols each)
    const uint32_t sb = smem_u32(sm);
    const uint32_t mb  = sb + (uint32_t)MB1F * 4u;
    const uint32_t mbe = mb + 32u;

    init_ring(mb, tid, 256);

    #pragma unroll
    for (int i = 0; i < 8; ++i) {
        int idx = tid + (i << 8);
        int r = idx >> 6, c4 = idx & 63;
        CP_ASYNC16(sb + (uint32_t)(r * PA + c4 * 4) * 4u,
                   A + (size_t)(row0 + r) * E_ + c4 * 4);
    }
    if (tid < 64)
        CP_ASYNC16(sb + (uint32_t)(XF1 + tid * 4) * 4u, bias + tid * 4);

    float acc[8][4];
    #pragma unroll
    for (int nt = 0; nt < 8; ++nt)
        #pragma unroll
        for (int q = 0; q < 4; ++q) acc[nt][q] = 0.f;

    const uint32_t a_base = sb
        + (uint32_t)((mwarp * 16 + (lane & 15)) * PA + ((lane >> 4) << 2)) * 4u;
    const uint32_t b_lane =
        (uint32_t)((nwarp * 64 + (lane & 7)) * PB + (((lane >> 3) & 1) << 2)) * 4u;

    produce_prep(Bmat, sb, mb, tid, 0);
    produce_prep(Bmat, sb, mb, tid, 1);
    produce_prep(Bmat, sb, mb, tid, 2);

    #pragma unroll 1
    for (int c = 0; c < NCH; ++c) {
        int cp = c + 3;
        if (cp < NCH) {
            int q2 = cp >> 2;
            if (q2 >= 1)
                MBAR_WAIT(mbe + (uint32_t)(cp & 3) * 8u, (q2 - 1) & 1);
            produce_prep(Bmat, sb, mb, tid, cp);
        }
        MBAR_WAIT(mb + (uint32_t)(c & 3) * 8u, (c >> 2) & 1);

        const uint32_t a_c = a_base + (uint32_t)c * 64u;
        const uint32_t b_c = sb + (uint32_t)(AF1 + (c & 3) * BSTG) * 4u + b_lane;
        #pragma unroll
        for (int ks = 0; ks < 2; ++ks) {
            uint32_t afr[4];
            ldsm_x4(afr, a_c + ks * 32u);
            uint32_t bfr[8][2];
            #pragma unroll
            for (int nt = 0; nt < 8; ++nt)
                ldsm_x2(bfr[nt], b_c + (uint32_t)nt * (8u * PB * 4u) + ks * 32u);
            #pragma unroll
            for (int nt = 0; nt < 8; ++nt)
                mma_tf32(acc[nt], afr, bfr[nt]);
        }
        MBAR_ARRIVE(mbe + (uint32_t)(c & 3) * 8u);
    }

    #pragma unroll
    for (int r2 = 0; r2 < 2; ++r2) {
        int row = row0 + mwarp * 16 + grp + r2 * 8;
        #pragma unroll
        for (int nt = 0; nt < 8; ++nt) {
            int col = nwarp * 64 + nt * 8 + tig * 2;
            float2 bv = *reinterpret_cast<const float2*>(sm + XF1 + col);
            float2 o  = make_float2(acc[nt][r2 * 2 + 0] + bv.x,
                                    acc[nt][r2 * 2 + 1] + bv.y);
            *reinterpret_cast<float2*>(outp + (size_t)row * E_ + col) = o;
        }
    }

    __threadfence();
    __syncthreads();
    if (tid == 0) atomicAdd(&g_prep_done, 1u);
}

// ======================= fused kernel ======================================
__global__ void __launch_bounds__(256, 1)
memcell_fused(const float* __restrict__ state, const float* __restrict__ U,
              const float* __restrict__ x, const float* __restrict__ keys,
              const float* __restrict__ V, const float* __restrict__ W,
              const float* __restrict__ bias, float* __restrict__ out)
{
    extern __shared__ float sm[];
    if (blockIdx.x < NC1) {
        // convert 2x256 halves of U to fp16 (covered by prep counter+fence)
        #pragma unroll
        for (int i = 0; i < 2; ++i) {
            size_t o = (size_t)blockIdx.x * 512 + threadIdx.x + i * 256;
            g_Uh[o] = __float2half_rn(U[o]);
        }
        prep_body(x, W, bias, g_c1, blockIdx.x * 32, sm);
    } else if (blockIdx.x == NC1) {
        prep_body(keys, V, g_zero, g_c2, 0, sm);
    } else {
        main_body(state, x, keys, out, sm, blockIdx.x - NPREP);
    }
}

// ===========================================================================
extern "C" void kernel_launch(void* const* d_in, const int* in_sizes, int n_in,
                              void* d_out, int out_size)
{
    const float* x     = (const float*)d_in[0];
    const float* state = (const float*)d_in[1];
    const float* keys  = (const float*)d_in[2];
    const float* U     = (const float*)d_in[3];
    const float* V     = (const float*)d_in[4];
    const float* W     = (const float*)d_in[5];
    const float* bias  = (const float*)d_in[6];
    float* out = (float*)d_out;

    cudaFuncSetAttribute(memcell_fused,
                         cudaFuncAttributeMaxDynamicSharedMemorySize, MAIN_SMEM);

    memcell_fused<<<NPREP + NMAIN, 256, MAIN_SMEM>>>(state, U, x, keys,
                                                     V, W, bias, out);
}

// round 17
// speedup vs baseline: 1.2757x; 1.0791x over previous
#include <cuda_runtime.h>
#include <cuda_fp16.h>
#include <math.h>
#include <stdint.h>

#define B_   4096
#define J_   32
#define E_   256
#define ROWS (B_ * J_)
#define NC1   (B_ / 32)              // 128 c1 CTAs (M=32 each)
#define NPREP (NC1 + 1)              // + 1 c2 CTA
#define NMAIN (ROWS / 128)           // 1024 main CTAs

// ======================= scratch (device globals) ==========================
__device__ float  g_c1[B_ * E_];         // bias + x @ W^T
__device__ float  g_c2[J_ * E_];         // keys @ V^T
__device__ float  g_zero[E_];            // zero "bias" for the c2 CTA
__device__ __half g_Uh[E_ * E_];         // U converted to fp16 (by prep)
__device__ unsigned int g_prep_done;
__device__ unsigned int g_main_done;

// ======================= PTX helpers =======================================
__device__ __forceinline__ uint32_t smem_u32(const void* p) {
    uint32_t a;
    asm("{ .reg .u64 t; cvta.to.shared.u64 t, %1; cvt.u32.u64 %0, t; }"
        : "=r"(a) : "l"(p));
    return a;
}

#define CP_ASYNC16(dst, src)                                                  \
    asm volatile("cp.async.cg.shared.global [%0], [%1], 16;"                  \
        :: "r"(dst), "l"(__cvta_generic_to_global((const void*)(src))) : "memory")
#define CP_COMMIT() asm volatile("cp.async.commit_group;" ::: "memory")
#define CP_WAIT0()  asm volatile("cp.async.wait_group 0;" ::: "memory")

#define MBAR_INIT(addr, cnt)                                                  \
    asm volatile("mbarrier.init.shared.b64 [%0], %1;" :: "r"(addr), "r"(cnt) : "memory")
#define CP_MBAR_ARRIVE(addr)                                                  \
    asm volatile("cp.async.mbarrier.arrive.noinc.shared.b64 [%0];"            \
        :: "r"(addr) : "memory")
#define MBAR_ARRIVE(addr)                                                     \
    asm volatile("mbarrier.arrive.shared.b64 _, [%0];" :: "r"(addr) : "memory")
#define MBAR_WAIT(addr, parity) do {                                          \
    asm volatile("{\n\t.reg .pred P;\n\t"                                     \
        "WL_%=:\n\t"                                                          \
        "mbarrier.try_wait.parity.shared.b64 P, [%0], %1;\n\t"                \
        "@P bra.uni WD_%=;\n\t"                                               \
        "bra.uni WL_%=;\n\t"                                                  \
        "WD_%=:\n\t}"                                                         \
        :: "r"(addr), "r"(parity) : "memory");                                \
} while (0)

__device__ __forceinline__ void mma_tf32(float* d, const uint32_t* a,
                                         const uint32_t* b) {
    asm volatile(
        "mma.sync.aligned.m16n8k8.row.col.f32.tf32.tf32.f32 "
        "{%0,%1,%2,%3}, {%4,%5,%6,%7}, {%8,%9}, {%0,%1,%2,%3};"
        : "+f"(d[0]), "+f"(d[1]), "+f"(d[2]), "+f"(d[3])
        : "r"(a[0]), "r"(a[1]), "r"(a[2]), "r"(a[3]), "r"(b[0]), "r"(b[1]));
}
__device__ __forceinline__ void mma_f16(float* d, const uint32_t* a,
                                        const uint32_t* b) {
    asm volatile(
        "mma.sync.aligned.m16n8k16.row.col.f32.f16.f16.f32 "
        "{%0,%1,%2,%3}, {%4,%5,%6,%7}, {%8,%9}, {%0,%1,%2,%3};"
        : "+f"(d[0]), "+f"(d[1]), "+f"(d[2]), "+f"(d[3])
        : "r"(a[0]), "r"(a[1]), "r"(a[2]), "r"(a[3]), "r"(b[0]), "r"(b[1]));
}

__device__ __forceinline__ void ldsm_x4(uint32_t* r, uint32_t addr) {
    asm volatile("ldmatrix.sync.aligned.m8n8.x4.shared.b16 {%0,%1,%2,%3}, [%4];"
        : "=r"(r[0]), "=r"(r[1]), "=r"(r[2]), "=r"(r[3]) : "r"(addr));
}
__device__ __forceinline__ void ldsm_x2(uint32_t* r, uint32_t addr) {
    asm volatile("ldmatrix.sync.aligned.m8n8.x2.shared.b16 {%0,%1}, [%2];"
        : "=r"(r[0]), "=r"(r[1]) : "r"(addr));
}

// ======================= smem layout =======================================
#define NCH   16                     // K chunks of 16
// ---- main CTA (fp16, 512 thr / 16 warps, warp tile 32x64, resident U) ----
#define PHB   528                    // fp16 row pitch bytes (264 halves)
#define UH_B  0                      // U fp16 tile: 256 x 528B = 135,168
#define AH_B  135168                 // A fp16 tile: 128 x 528B = 67,584
#define XF_F  50688                  // x tile (4x256 fp32), float offset
#define GF_F  51712                  // gate[128]
#define RED_F 51840                  // norm red[128*4]
#define INV_F 52352                  // inv[128]
#define SMEMF 52480                  // floats
#define MAIN_SMEM (SMEMF * 4)        // 209,920 bytes
// gate partials alias the (not yet staged) U region: pred[r*64+c4], 32KB
// ---- prep CTA (tf32, R13-proven 512-thr layout) ----
#define PA    260
#define PB    20
#define BSTG  5120
#define AF1   8320
#define XF1   (AF1 + 4 * BSTG)       // 28800
#define MB1F  (XF1 + 256)            // 29056  (< SMEMF ✓)

__device__ __forceinline__ void init_ring(uint32_t mb, int tid, int cnt)
{
    if (tid == 0) {
        #pragma unroll
        for (int s = 0; s < 4; ++s) {
            MBAR_INIT(mb + s * 8u, cnt);
            MBAR_INIT(mb + 32u + s * 8u, cnt);
        }
    }
    __syncthreads();
}

// ======================= main-CTA body (fp16, 16 warps, fused gate) ========
__device__ void main_body(const float* __restrict__ state,
                          const float* __restrict__ x,
                          const float* __restrict__ keys,
                          float* __restrict__ out,
                          float* sm, int bid)
{
    const int tid  = threadIdx.x;
    const int lane = tid & 31;
    const int wid  = tid >> 5;
    const int grp  = lane >> 2;
    const int tig  = lane & 3;
    const int mwarp = wid >> 2;       // 0..3 (32 rows each)
    const int nwarp = wid & 3;        // 0..3 (64 cols each)
    const int row0 = bid * 128;
    const uint32_t sb = smem_u32(sm);
    char* smc = reinterpret_cast<char*>(sm);
    float* pred = sm;                 // gate partials alias U region

    // ---- stage x (4 rows x 256 fp32) ----
    if (tid < 256)
        reinterpret_cast<float4*>(sm + XF_F)[tid] =
            reinterpret_cast<const float4*>(x + (size_t)(row0 >> 5) * E_)[tid];
    __syncthreads();

    // ---- A staging + fused gate partials:
    //      LDG state -> cvt fp16 -> STS;  p = (s+key).x -> pred[r*64+c4]
    #pragma unroll 4
    for (int i = 0; i < 16; ++i) {
        int idx = tid + (i << 9);
        int r = idx >> 6, c4 = idx & 63;
        float4 sv = reinterpret_cast<const float4*>(
                        state + (size_t)(row0 + r) * E_)[c4];
        float4 kv = reinterpret_cast<const float4*>(
                        keys + (size_t)(r & 31) * E_)[c4];
        float4 xv = reinterpret_cast<const float4*>(
                        sm + XF_F + (r >> 5) * 256)[c4];
        pred[r * 64 + c4] = (sv.x + kv.x) * xv.x + (sv.y + kv.y) * xv.y
                          + (sv.z + kv.z) * xv.z + (sv.w + kv.w) * xv.w;
        __half2 h0 = __floats2half2_rn(sv.x, sv.y);
        __half2 h1 = __floats2half2_rn(sv.z, sv.w);
        uint2 u; u.x = *(uint32_t*)&h0; u.y = *(uint32_t*)&h1;
        *reinterpret_cast<uint2*>(smc + AH_B + r * PHB + c4 * 8) = u;
    }
    __syncthreads();

    // ---- reduce partials -> gate[128]  (thread (r,q): 16 values + quad) ---
    {
        int r = tid >> 2, q = tid & 3;
        const float* pr = pred + r * 64 + q * 16;
        float s = 0.f;
        #pragma unroll
        for (int t = 0; t < 16; ++t) s += pr[t];
        s += __shfl_xor_sync(0xffffffffu, s, 1);
        s += __shfl_xor_sync(0xffffffffu, s, 2);
        if (q == 0)
            sm[GF_F + r] = 1.f / (1.f + expf(-s));
    }

    // ---- wait prep (needs g_Uh) ----
    if (tid == 0)
        while (atomicAdd(&g_prep_done, 0u) < (unsigned)NPREP) {}
    __syncthreads();   // gate done + pred reads done before U overwrites

    // ---- stage U fp16 (256 x 256): 8192 x 16B, 16 per thread ----
    #pragma unroll
    for (int i = 0; i < 16; ++i) {
        int idx = tid + (i << 9);
        int f = idx >> 5, c16 = idx & 31;
        CP_ASYNC16(sb + (uint32_t)(UH_B + f * PHB + c16 * 16),
                   (const __half*)g_Uh + (size_t)f * E_ + c16 * 8);
    }
    CP_COMMIT();
    CP_WAIT0();
    __syncthreads();

    float acc[2][8][4];
    #pragma unroll
    for (int mt = 0; mt < 2; ++mt)
        #pragma unroll
        for (int nt = 0; nt < 8; ++nt)
            #pragma unroll
            for (int q = 0; q < 4; ++q) acc[mt][nt][q] = 0.f;

    // ldmatrix lane-address bases (bytes) -- R13-proven 16-warp mappings
    const uint32_t a_base = sb + AH_B
        + (uint32_t)((mwarp * 32 + (lane & 15)) * PHB + ((lane >> 4) << 4));
    const uint32_t b_base = sb + UH_B
        + (uint32_t)((nwarp * 64 + (lane & 7)) * PHB + (((lane >> 3) & 1) << 4));

    // ---- mainloop: straight-line, fully resident, zero synchronization ----
    #pragma unroll 2
    for (int c = 0; c < NCH; ++c) {
        const uint32_t a_c = a_base + (uint32_t)c * 32u;
        const uint32_t b_c = b_base + (uint32_t)c * 32u;
        uint32_t afr[2][4];
        ldsm_x4(afr[0], a_c);
        ldsm_x4(afr[1], a_c + 16u * PHB);
        uint32_t bfr[8][2];
        #pragma unroll
        for (int nt = 0; nt < 8; ++nt)
            ldsm_x2(bfr[nt], b_c + (uint32_t)nt * (8u * PHB));
        #pragma unroll
        for (int nt = 0; nt < 8; ++nt) {
            mma_f16(acc[0][nt], afr[0], bfr[nt]);
            mma_f16(acc[1][nt], afr[1], bfr[nt]);
        }
    }
    __syncthreads();

    // ---- epilogue pass 1: v = s + g*relu(acc + c1 + c2) -> Ah (fp16) ----
    float* red = sm + RED_F;
    float* inv = sm + INV_F;
    #pragma unroll
    for (int mt = 0; mt < 2; ++mt) {
        #pragma unroll
        for (int r2 = 0; r2 < 2; ++r2) {
            int rl   = mwarp * 32 + mt * 16 + grp + r2 * 8;
            int grow = row0 + rl;
            float gv = sm[GF_F + rl];
            const float* c1r = g_c1 + (size_t)(grow >> 5) * E_;
            const float* c2r = g_c2 + (size_t)(grow & 31) * E_;
            float ss = 0.f;
            #pragma unroll
            for (int nt = 0; nt < 8; ++nt) {
                int col = nwarp * 64 + nt * 8 + tig * 2;
                uint32_t su = *reinterpret_cast<uint32_t*>(
                                  smc + AH_B + rl * PHB + col * 2);
                float2 svv = __half22float2(*reinterpret_cast<__half2*>(&su));
                float2 c1v = *reinterpret_cast<const float2*>(c1r + col);
                float2 c2v = *reinterpret_cast<const float2*>(c2r + col);
                float d0 = acc[mt][nt][r2 * 2 + 0] + c1v.x + c2v.x;
                float d1 = acc[mt][nt][r2 * 2 + 1] + c1v.y + c2v.y;
                float v0 = svv.x + gv * fmaxf(d0, 0.f);
                float v1 = svv.y + gv * fmaxf(d1, 0.f);
                ss += v0 * v0 + v1 * v1;
                __half2 hv = __floats2half2_rn(v0, v1);
                *reinterpret_cast<uint32_t*>(smc + AH_B + rl * PHB + col * 2)
                    = *(uint32_t*)&hv;
            }
            ss += __shfl_xor_sync(0xffffffffu, ss, 1);
            ss += __shfl_xor_sync(0xffffffffu, ss, 2);
            if (tig == 0) red[rl * 4 + nwarp] = ss;
        }
    }
    __syncthreads();
    if (tid < 128) {
        float s = red[tid * 4] + red[tid * 4 + 1]
                + red[tid * 4 + 2] + red[tid * 4 + 3];
        inv[tid] = 1.f / (sqrtf(s) + 1e-8f);
    }
    __syncthreads();

    // ---- epilogue pass 2: coalesced normalized writeback (fp16 -> fp32) ---
    #pragma unroll
    for (int i = 0; i < 8; ++i) {
        int idx = tid + (i << 9);
        int r = idx >> 5, c8 = idx & 31;
        float iv = inv[r];
        uint4 u = *reinterpret_cast<uint4*>(smc + AH_B + r * PHB + c8 * 16);
        const __half2* hp = reinterpret_cast<const __half2*>(&u);
        float2 f0 = __half22float2(hp[0]), f1 = __half22float2(hp[1]);
        float2 f2 = __half22float2(hp[2]), f3 = __half22float2(hp[3]);
        float4 o0 = make_float4(f0.x * iv, f0.y * iv, f1.x * iv, f1.y * iv);
        float4 o1 = make_float4(f2.x * iv, f2.y * iv, f3.x * iv, f3.y * iv);
        float4* op = reinterpret_cast<float4*>(out + (size_t)(row0 + r) * E_
                                               + c8 * 8);
        op[0] = o0; op[1] = o1;
    }

    // ---- last main CTA resets the handshake counters ----
    __syncthreads();
    if (tid == 0) {
        unsigned v = atomicAdd(&g_main_done, 1u);
        if (v == (unsigned)(NMAIN - 1)) {
            atomicExch(&g_prep_done, 0u);
            atomicExch(&g_main_done, 0u);
        }
    }
}

// ======================= prep-CTA body (tf32 M=32, 512 thr, R13-proven) ====
__device__ __forceinline__ void produce_prep(const float* __restrict__ Bg,
                                             uint32_t sb, uint32_t mb,
                                             int tid, int p)
{
    uint32_t bst = sb + (uint32_t)(AF1 + (p & 3) * BSTG) * 4u;
    #pragma unroll
    for (int i = 0; i < 2; ++i) {
        int idx = tid + (i << 9);
        int f = idx >> 2, k4 = idx & 3;
        CP_ASYNC16(bst + (uint32_t)(f * PB + k4 * 4) * 4u,
                   Bg + (size_t)f * E_ + p * 16 + k4 * 4);
    }
    CP_MBAR_ARRIVE(mb + (uint32_t)(p & 3) * 8u);
}

__device__ void prep_body(const float* __restrict__ A,
                          const float* __restrict__ Bmat,
                          const float* __restrict__ bias,
                          float* __restrict__ outp, int row0,
                          float* sm)
{
    const int tid  = threadIdx.x;
    const int lane = tid & 31;
    const int wid  = tid >> 5;
    const int grp  = lane >> 2;
    const int tig  = lane & 3;
    const int mwarp = wid >> 3;       // 0..1 (16 rows each)
    const int nwarp = wid & 7;        // 0..7 (32 cols each)
    const uint32_t sb = smem_u32(sm);
    const uint32_t mb  = sb + (uint32_t)MB1F * 4u;
    const uint32_t mbe = mb + 32u;

    init_ring(mb, tid, 512);

    #pragma unroll
    for (int i = 0; i < 4; ++i) {
        int idx = tid + (i << 9);
        int r = idx >> 6, c4 = idx & 63;
        CP_ASYNC16(sb + (uint32_t)(r * PA + c4 * 4) * 4u,
                   A + (size_t)(row0 + r) * E_ + c4 * 4);
    }
    if (tid < 64)
        CP_ASYNC16(sb + (uint32_t)(XF1 + tid * 4) * 4u, bias + tid * 4);

    float acc[4][4];
    #pragma unroll
    for (int nt = 0; nt < 4; ++nt)
        #pragma unroll
        for (int q = 0; q < 4; ++q) acc[nt][q] = 0.f;

    const uint32_t a_base = sb
        + (uint32_t)((mwarp * 16 + (lane & 15)) * PA + ((lane >> 4) << 2)) * 4u;
    const uint32_t b_lane =
        (uint32_t)((nwarp * 32 + (lane & 7)) * PB + (((lane >> 3) & 1) << 2)) * 4u;

    produce_prep(Bmat, sb, mb, tid, 0);
    produce_prep(Bmat, sb, mb, tid, 1);
    produce_prep(Bmat, sb, mb, tid, 2);

    #pragma unroll 1
    for (int c = 0; c < NCH; ++c) {
        int cp = c + 3;
        if (cp < NCH) {
            int q2 = cp >> 2;
            if (q2 >= 1)
                MBAR_WAIT(mbe + (uint32_t)(cp & 3) * 8u, (q2 - 1) & 1);
            produce_prep(Bmat, sb, mb, tid, cp);
        }
        MBAR_WAIT(mb + (uint32_t)(c & 3) * 8u, (c >> 2) & 1);

        const uint32_t a_c = a_base + (uint32_t)c * 64u;
        const uint32_t b_c = sb + (uint32_t)(AF1 + (c & 3) * BSTG) * 4u + b_lane;
        #pragma unroll
        for (int ks = 0; ks < 2; ++ks) {
            uint32_t afr[4];
            ldsm_x4(afr, a_c + ks * 32u);
            uint32_t bfr[4][2];
            #pragma unroll
            for (int nt = 0; nt < 4; ++nt)
                ldsm_x2(bfr[nt], b_c + (uint32_t)nt * (8u * PB * 4u) + ks * 32u);
            #pragma unroll
            for (int nt = 0; nt < 4; ++nt)
                mma_tf32(acc[nt], afr, bfr[nt]);
        }
        MBAR_ARRIVE(mbe + (uint32_t)(c & 3) * 8u);
    }

    #pragma unroll
    for (int r2 = 0; r2 < 2; ++r2) {
        int row = row0 + mwarp * 16 + grp + r2 * 8;
        #pragma unroll
        for (int nt = 0; nt < 4; ++nt) {
            int col = nwarp * 32 + nt * 8 + tig * 2;
            float2 bv = *reinterpret_cast<const float2*>(sm + XF1 + col);
            float2 o  = make_float2(acc[nt][r2 * 2 + 0] + bv.x,
                                    acc[nt][r2 * 2 + 1] + bv.y);
            *reinterpret_cast<float2*>(outp + (size_t)row * E_ + col) = o;
        }
    }

    __threadfence();
    __syncthreads();
    if (tid == 0) atomicAdd(&g_prep_done, 1u);
}

// ======================= fused kernel ======================================
__global__ void __launch_bounds__(512, 1)
memcell_fused(const float* __restrict__ state, const float* __restrict__ U,
              const float* __restrict__ x, const float* __restrict__ keys,
              const float* __restrict__ V, const float* __restrict__ W,
              const float* __restrict__ bias, float* __restrict__ out)
{
    extern __shared__ float sm[];
    if (blockIdx.x < NC1) {
        // convert 512 elems of U to fp16 (covered by prep counter + fence)
        size_t o = (size_t)blockIdx.x * 512 + threadIdx.x;
        g_Uh[o] = __float2half_rn(U[o]);
        prep_body(x, W, bias, g_c1, blockIdx.x * 32, sm);
    } else if (blockIdx.x == NC1) {
        prep_body(keys, V, g_zero, g_c2, 0, sm);
    } else {
        main_body(state, x, keys, out, sm, blockIdx.x - NPREP);
    }
}

// ===========================================================================
extern "C" void kernel_launch(void* const* d_in, const int* in_sizes, int n_in,
                              void* d_out, int out_size)
{
    const float* x     = (const float*)d_in[0];
    const float* state = (const float*)d_in[1];
    const float* keys  = (const float*)d_in[2];
    const float* U     = (const float*)d_in[3];
    const float* V     = (const float*)d_in[4];
    const float* W     = (const float*)d_in[5];
    const float* bias  = (const float*)d_in[6];
    float* out = (float*)d_out;

    cudaFuncSetAttribute(memcell_fused,
                         cudaFuncAttributeMaxDynamicSharedMemorySize, MAIN_SMEM);

    memcell_fused<<<NPREP + NMAIN, 512, MAIN_SMEM>>>(state, U, x, keys,
                                                     V, W, bias, out);
}